// round 13
// baseline (speedup 1.0000x reference)
#include <cuda_runtime.h>
#include <cuda_bf16.h>
#include <cstdint>

// ---------------- problem constants ----------------
#define NB   8192
#define ND   1024
#define NR   64
#define NRR  4096
#define NT_W 32              // 4096 / 128

// ---------------- int8 W-gemm tiling ----------------
#define GBM 128
#define GBN 128
#define SKE 64               // int8 K elems per stage
#define S8_LDSW 80           // bytes per smem row (64 + 16 skew)
#define S8_MAT   (128 * S8_LDSW)     // 10240
#define S8_STAGE (4 * S8_MAT)        // 40960
#define S8_SMEM  (2 * S8_STAGE)      // 81920

// ---------------- bf16 u-gemm tiling (BKE=64) ----------------
#define UB_LDSW 36           // u32 row stride (32 + 4 skew)
#define UB_MAT   (128 * UB_LDSW * 4) // 18432
#define UB_STAGE (4 * UB_MAT)        // 73728
#define UB_SMEM  (2 * UB_STAGE)      // 147456

// ---------------- static device scratch ----------------
__device__ __nv_bfloat16 g_xhi[(size_t)NB * ND];
__device__ __nv_bfloat16 g_xlo[(size_t)NB * ND];
__device__ __nv_bfloat16 g_uhi[(size_t)128 * ND];
__device__ __nv_bfloat16 g_ulo[(size_t)128 * ND];
__device__ char  g_xq1[(size_t)NB * ND];
__device__ char  g_xq0[(size_t)NB * ND];
__device__ char  g_wq1[(size_t)NRR * ND];
__device__ char  g_wq0[(size_t)NRR * ND];
__device__ float g_invc[NB];
__device__ float g_invd[NRR];
__device__ float g_u2[(size_t)2 * NB * NR];
__device__ float g_hp[(size_t)NB * NT_W * NR];
__device__ float g_h [(size_t)NB * NR];
__device__ float g_act[(size_t)NB * ND];

// ---------------- helpers ----------------
__device__ __forceinline__ uint32_t smem_u32(const void* p) {
    uint32_t a;
    asm("{ .reg .u64 t; cvta.to.shared.u64 t, %1; cvt.u32.u64 %0, t; }"
        : "=r"(a) : "l"(p));
    return a;
}
__device__ __forceinline__ void cpa16(uint32_t s, const void* g) {
    asm volatile("cp.async.cg.shared.global [%0], [%1], 16;\n" :: "r"(s), "l"(g));
}
#define CP_COMMIT() asm volatile("cp.async.commit_group;\n" ::: "memory")
#define CP_WAIT(n)  asm volatile("cp.async.wait_group %0;\n" :: "n"(n) : "memory")

#define MMA_BF16(acc, a0, a1, a2, a3, b0, b1)                                  \
    asm("mma.sync.aligned.m16n8k16.row.col.f32.bf16.bf16.f32 "                 \
        "{%0,%1,%2,%3}, {%4,%5,%6,%7}, {%8,%9}, {%0,%1,%2,%3};\n"              \
        : "+f"(acc[0]), "+f"(acc[1]), "+f"(acc[2]), "+f"(acc[3])               \
        : "r"(a0), "r"(a1), "r"(a2), "r"(a3), "r"(b0), "r"(b1))

#define MMA_S8(acc, a0, a1, a2, a3, b0, b1)                                    \
    asm("mma.sync.aligned.m16n8k32.row.col.s32.s8.s8.s32 "                     \
        "{%0,%1,%2,%3}, {%4,%5,%6,%7}, {%8,%9}, {%0,%1,%2,%3};\n"              \
        : "+r"(acc[0]), "+r"(acc[1]), "+r"(acc[2]), "+r"(acc[3])               \
        : "r"(a0), "r"(a1), "r"(a2), "r"(a3), "r"(b0), "r"(b1))

#define LDSM_X4(r, addr)                                                       \
    asm volatile("ldmatrix.sync.aligned.m8n8.x4.shared.b16 {%0,%1,%2,%3}, [%4];" \
        : "=r"((r)[0]), "=r"((r)[1]), "=r"((r)[2]), "=r"((r)[3]) : "r"(addr))

// ---------------------------------------------------------------------------
// Per-row quantization: 1 block per row of 1024 floats.
// Emits 16-bit fixed point as two s8 planes (q = 256*q1 + q0'), row scale,
// and (optionally) bf16 hi/lo split for the u-GEMM.
// ---------------------------------------------------------------------------
template<bool BF16>
__global__ __launch_bounds__(256)
void quant_rows(const float* __restrict__ in, char* __restrict__ q1p,
                char* __restrict__ q0p, float* __restrict__ inv,
                __nv_bfloat16* __restrict__ hi, __nv_bfloat16* __restrict__ lo)
{
    __shared__ float smax[8];
    const int row = blockIdx.x, tid = threadIdx.x;
    const float4 v = ((const float4*)(in + (size_t)row * ND))[tid];
    float m = fmaxf(fmaxf(fabsf(v.x), fabsf(v.y)), fmaxf(fabsf(v.z), fabsf(v.w)));
#pragma unroll
    for (int o = 16; o; o >>= 1) m = fmaxf(m, __shfl_xor_sync(~0u, m, o));
    if ((tid & 31) == 0) smax[tid >> 5] = m;
    __syncthreads();
    float M = smax[0];
#pragma unroll
    for (int i = 1; i < 8; i++) M = fmaxf(M, smax[i]);
    const float c = (M > 0.f) ? 32512.f / M : 0.f;
    if (tid == 0) inv[row] = (M > 0.f) ? M / 32512.f : 0.f;

    const float f[4] = {v.x, v.y, v.z, v.w};
    uint32_t p1 = 0, p0 = 0;
#pragma unroll
    for (int j = 0; j < 4; j++) {
        int q = __float2int_rn(f[j] * c);
        q = max(-32512, min(32512, q));
        const int q0 = ((q + 128) & 255) - 128;
        const int q1 = (q - q0) >> 8;
        p1 |= (uint32_t)(q1 & 255) << (8 * j);
        p0 |= (uint32_t)(q0 & 255) << (8 * j);
    }
    ((uint32_t*)(q1p + (size_t)row * ND))[tid] = p1;
    ((uint32_t*)(q0p + (size_t)row * ND))[tid] = p0;

    if (BF16) {
        __nv_bfloat16 hh[4], ll[4];
#pragma unroll
        for (int j = 0; j < 4; j++) {
            hh[j] = __float2bfloat16_rn(f[j]);
            ll[j] = __float2bfloat16_rn(f[j] - __bfloat162float(hh[j]));
        }
        __nv_bfloat162* hp = (__nv_bfloat162*)(hi + (size_t)row * ND) + 2 * tid;
        __nv_bfloat162* lp = (__nv_bfloat162*)(lo + (size_t)row * ND) + 2 * tid;
        hp[0] = __halves2bfloat162(hh[0], hh[1]);
        hp[1] = __halves2bfloat162(hh[2], hh[3]);
        lp[0] = __halves2bfloat162(ll[0], ll[1]);
        lp[1] = __halves2bfloat162(ll[2], ll[3]);
    }
}

// U [64 x 1024] -> padded [128 x 1024] hi/lo with zero rows 64..127
__global__ __launch_bounds__(256)
void conv_upad(const float* __restrict__ U, __nv_bfloat162* __restrict__ hi,
               __nv_bfloat162* __restrict__ lo)
{
    const int i = blockIdx.x * 256 + threadIdx.x;
    if (i >= 128 * ND / 4) return;
    const int row = (i * 4) >> 10;
    float4 v = make_float4(0.f, 0.f, 0.f, 0.f);
    if (row < NR) v = ((const float4*)U)[i];
    const float f[4] = {v.x, v.y, v.z, v.w};
    __nv_bfloat16 hh[4], ll[4];
#pragma unroll
    for (int j = 0; j < 4; j++) {
        hh[j] = __float2bfloat16_rn(f[j]);
        ll[j] = __float2bfloat16_rn(f[j] - __bfloat162float(hh[j]));
    }
    hi[2 * i]     = __halves2bfloat162(hh[0], hh[1]);
    hi[2 * i + 1] = __halves2bfloat162(hh[2], hh[3]);
    lo[2 * i]     = __halves2bfloat162(ll[0], ll[1]);
    lo[2 * i + 1] = __halves2bfloat162(ll[2], ll[3]);
}

// ---------------------------------------------------------------------------
// u-GEMM: 3xBF16, BKE=64 (proven R10 config).  blockIdx.x = K-slice (0/1).
// Stores D cols [0,64) to out + slice*NB*NR.
// ---------------------------------------------------------------------------
__global__ __launch_bounds__(256)
void gemm_u(const __nv_bfloat16* __restrict__ Ahi_g, const __nv_bfloat16* __restrict__ Alo_g,
            const __nv_bfloat16* __restrict__ Bhi_g, const __nv_bfloat16* __restrict__ Blo_g,
            float* __restrict__ out)
{
    extern __shared__ char dynsmem[];
    const uint32_t sbase = smem_u32(dynsmem);

    const int tid = threadIdx.x, warp = tid >> 5, lane = tid & 31;
    const int wm = (warp & 3) * 32, wn = (warp >> 2) * 64;
    const int g = lane >> 2, tg = lane & 3;
    const int nt = blockIdx.x, mt = blockIdx.y;
    const size_t arow0 = (size_t)mt * GBM;
    const int kbase = nt * (ND / 2);

    float acc[2][8][4];
#pragma unroll
    for (int i = 0; i < 2; i++)
#pragma unroll
        for (int j = 0; j < 8; j++)
#pragma unroll
            for (int k = 0; k < 4; k++) acc[i][j][k] = 0.f;

    const int l8 = lane & 7;
    uint32_t aOffB[2], bOffB[4];
#pragma unroll
    for (int mf = 0; mf < 2; mf++)
        aOffB[mf] = (uint32_t)(((wm + mf * 16 + l8 + ((lane >> 3) & 1) * 8) * UB_LDSW
                                + (lane >> 4) * 4) * 4);
#pragma unroll
    for (int p = 0; p < 4; p++)
        bOffB[p] = (uint32_t)(((wn + p * 16 + l8 + ((lane >> 4) & 1) * 8) * UB_LDSW
                               + ((lane >> 3) & 1) * 4) * 4);

    auto load_stage = [&](int stage, int buf) {
        const uint32_t base = sbase + buf * UB_STAGE;
        const int k0 = kbase + stage * 64;
#pragma unroll
        for (int it = 0; it < 4; it++) {
            const int t = tid + it * 256;
            const int row = t >> 3, c = t & 7;
            const uint32_t so = (uint32_t)(row * (UB_LDSW * 4) + c * 16);
            const size_t ga = (arow0 + row) * ND + k0 + c * 8;
            const size_t gb = (size_t)row * ND + k0 + c * 8;
            cpa16(base + so,              Ahi_g + ga);
            cpa16(base + UB_MAT + so,     Alo_g + ga);
            cpa16(base + 2 * UB_MAT + so, Bhi_g + gb);
            cpa16(base + 3 * UB_MAT + so, Blo_g + gb);
        }
        CP_COMMIT();
    };

    load_stage(0, 0);

    for (int i = 0; i < 8; i++) {
        if (i + 1 < 8) { load_stage(i + 1, (i + 1) & 1); CP_WAIT(1); }
        else           { CP_WAIT(0); }
        __syncthreads();

        const uint32_t stb = sbase + (i & 1) * UB_STAGE;
#pragma unroll
        for (int ks = 0; ks < 4; ks++) {
            const uint32_t kob = (uint32_t)(ks * 32);
            uint32_t ah[2][4], al[2][4], bh[4][4], bl[4][4];
#pragma unroll
            for (int mf = 0; mf < 2; mf++) {
                LDSM_X4(ah[mf], stb + aOffB[mf] + kob);
                LDSM_X4(al[mf], stb + UB_MAT + aOffB[mf] + kob);
            }
#pragma unroll
            for (int p = 0; p < 4; p++) {
                LDSM_X4(bh[p], stb + 2 * UB_MAT + bOffB[p] + kob);
                LDSM_X4(bl[p], stb + 3 * UB_MAT + bOffB[p] + kob);
            }
#pragma unroll
            for (int p = 0; p < 4; p++)
#pragma unroll
                for (int mf = 0; mf < 2; mf++) {
                    MMA_BF16(acc[mf][2 * p],     ah[mf][0], ah[mf][1], ah[mf][2], ah[mf][3], bh[p][0], bh[p][1]);
                    MMA_BF16(acc[mf][2 * p + 1], ah[mf][0], ah[mf][1], ah[mf][2], ah[mf][3], bh[p][2], bh[p][3]);
                }
#pragma unroll
            for (int p = 0; p < 4; p++)
#pragma unroll
                for (int mf = 0; mf < 2; mf++) {
                    MMA_BF16(acc[mf][2 * p],     ah[mf][0], ah[mf][1], ah[mf][2], ah[mf][3], bl[p][0], bl[p][1]);
                    MMA_BF16(acc[mf][2 * p + 1], ah[mf][0], ah[mf][1], ah[mf][2], ah[mf][3], bl[p][2], bl[p][3]);
                }
#pragma unroll
            for (int p = 0; p < 4; p++)
#pragma unroll
                for (int mf = 0; mf < 2; mf++) {
                    MMA_BF16(acc[mf][2 * p],     al[mf][0], al[mf][1], al[mf][2], al[mf][3], bh[p][0], bh[p][1]);
                    MMA_BF16(acc[mf][2 * p + 1], al[mf][0], al[mf][1], al[mf][2], al[mf][3], bh[p][2], bh[p][3]);
                }
        }
        __syncthreads();
    }

    float* o = out + (size_t)nt * NB * NR;
    if (wn == 0) {
#pragma unroll
        for (int mf = 0; mf < 2; mf++) {
#pragma unroll
            for (int nf = 0; nf < 8; nf++) {
                const size_t row = arow0 + wm + mf * 16 + g;
                const int col = nf * 8 + tg * 2;
                *(float2*)(o + row * NR + col) =
                    make_float2(acc[mf][nf][0], acc[mf][nf][1]);
                *(float2*)(o + (row + 8) * NR + col) =
                    make_float2(acc[mf][nf][2], acc[mf][nf][3]);
            }
        }
    }
}

// ---------------------------------------------------------------------------
// int8 W-GEMM + fused contract.  q = 256*q1 + q0' (s8 planes); per k-step
// 3 passes: q1*p1 -> acc_hi, q1*p0' and q0'*p1 -> acc_mid.  Dropped q0'p0'
// term ~6e-5 relative noise.  W = (65536*hi + 256*mid) * invc[m] * invd[n].
// Emits hp[m][nt][s] = sum_j u[m, nt*2+j] * (W[m, j*64+s] + bm[...]).
// ---------------------------------------------------------------------------
__global__ __launch_bounds__(256)
void gemm_s8(const char* __restrict__ Aq1, const char* __restrict__ Aq0,
             const char* __restrict__ Bq1, const char* __restrict__ Bq0,
             const float* __restrict__ invc, const float* __restrict__ invd,
             const float* __restrict__ uvec, const float* __restrict__ bmvec,
             float* __restrict__ out)
{
    extern __shared__ char dynsmem[];
    __shared__ float sbm[128], sinvd[128];
    const uint32_t sbase = smem_u32(dynsmem);

    const int tid = threadIdx.x, warp = tid >> 5, lane = tid & 31;
    const int wm = (warp & 3) * 32, wn = (warp >> 2) * 64;
    const int g = lane >> 2, tg = lane & 3;
    const int nt = blockIdx.x, mt = blockIdx.y;
    const size_t arow0 = (size_t)mt * GBM;
    const size_t brow0 = (size_t)nt * GBN;

    if (tid < 128) {
        sbm[tid]   = bmvec[nt * 128 + tid];
        sinvd[tid] = invd[nt * 128 + tid];
    }

    int acch[2][8][4], accm[2][8][4];
#pragma unroll
    for (int i = 0; i < 2; i++)
#pragma unroll
        for (int j = 0; j < 8; j++)
#pragma unroll
            for (int k = 0; k < 4; k++) { acch[i][j][k] = 0; accm[i][j][k] = 0; }

    const int l8 = lane & 7;
    uint32_t aOff[2], bOff[4];
#pragma unroll
    for (int mf = 0; mf < 2; mf++)
        aOff[mf] = (uint32_t)((wm + mf * 16 + l8 + ((lane >> 3) & 1) * 8) * S8_LDSW
                              + (lane >> 4) * 16);
#pragma unroll
    for (int p = 0; p < 4; p++)
        bOff[p] = (uint32_t)((wn + p * 16 + l8 + ((lane >> 4) & 1) * 8) * S8_LDSW
                             + ((lane >> 3) & 1) * 16);

    auto load_stage = [&](int stage, int buf) {
        const uint32_t base = sbase + buf * S8_STAGE;
        const int k0 = stage * SKE;
#pragma unroll
        for (int it = 0; it < 2; it++) {
            const int t = tid + it * 256;          // 0..511
            const int row = t >> 2, c = t & 3;
            const uint32_t so = (uint32_t)(row * S8_LDSW + c * 16);
            const size_t ga = (arow0 + row) * ND + k0 + c * 16;
            const size_t gb = (brow0 + row) * ND + k0 + c * 16;
            cpa16(base + so,              Aq1 + ga);
            cpa16(base + S8_MAT + so,     Aq0 + ga);
            cpa16(base + 2 * S8_MAT + so, Bq1 + gb);
            cpa16(base + 3 * S8_MAT + so, Bq0 + gb);
        }
        CP_COMMIT();
    };

    load_stage(0, 0);

    for (int i = 0; i < ND / SKE; i++) {           // 16 stages
        if (i + 1 < ND / SKE) { load_stage(i + 1, (i + 1) & 1); CP_WAIT(1); }
        else                  { CP_WAIT(0); }
        __syncthreads();

        const uint32_t stb = sbase + (i & 1) * S8_STAGE;
#pragma unroll
        for (int ks = 0; ks < 2; ks++) {           // k32 per step
            const uint32_t kob = (uint32_t)(ks * 32);
            uint32_t a1[2][4], a0[2][4], b1[4][4], b0[4][4];
#pragma unroll
            for (int mf = 0; mf < 2; mf++) {
                LDSM_X4(a1[mf], stb + aOff[mf] + kob);
                LDSM_X4(a0[mf], stb + S8_MAT + aOff[mf] + kob);
            }
#pragma unroll
            for (int p = 0; p < 4; p++) {
                LDSM_X4(b1[p], stb + 2 * S8_MAT + bOff[p] + kob);
                LDSM_X4(b0[p], stb + 3 * S8_MAT + bOff[p] + kob);
            }
            // pass 1: q1*p1 -> acc_hi
#pragma unroll
            for (int p = 0; p < 4; p++)
#pragma unroll
                for (int mf = 0; mf < 2; mf++) {
                    MMA_S8(acch[mf][2 * p],     a1[mf][0], a1[mf][1], a1[mf][2], a1[mf][3], b1[p][0], b1[p][1]);
                    MMA_S8(acch[mf][2 * p + 1], a1[mf][0], a1[mf][1], a1[mf][2], a1[mf][3], b1[p][2], b1[p][3]);
                }
            // pass 2: q1*p0' -> acc_mid
#pragma unroll
            for (int p = 0; p < 4; p++)
#pragma unroll
                for (int mf = 0; mf < 2; mf++) {
                    MMA_S8(accm[mf][2 * p],     a1[mf][0], a1[mf][1], a1[mf][2], a1[mf][3], b0[p][0], b0[p][1]);
                    MMA_S8(accm[mf][2 * p + 1], a1[mf][0], a1[mf][1], a1[mf][2], a1[mf][3], b0[p][2], b0[p][3]);
                }
            // pass 3: q0'*p1 -> acc_mid
#pragma unroll
            for (int p = 0; p < 4; p++)
#pragma unroll
                for (int mf = 0; mf < 2; mf++) {
                    MMA_S8(accm[mf][2 * p],     a0[mf][0], a0[mf][1], a0[mf][2], a0[mf][3], b1[p][0], b1[p][1]);
                    MMA_S8(accm[mf][2 * p + 1], a0[mf][0], a0[mf][1], a0[mf][2], a0[mf][3], b1[p][2], b1[p][3]);
                }
        }
        __syncthreads();
    }

    // ---- fused contract epilogue ----
    float* part = (float*)dynsmem;
    for (int idx = tid; idx < 128 * 65; idx += 256) part[idx] = 0.f;
    __syncthreads();

    const int j = warp >> 2;                       // r-block within tile (0/1)
    const int ridx = nt * 2 + j;
    float um[4], ic[4];
#pragma unroll
    for (int mf = 0; mf < 2; mf++) {
        const size_t m0 = arow0 + wm + mf * 16 + g;
        const size_t m1 = m0 + 8;
        um[mf * 2 + 0] = uvec[m0 * NR + ridx] + uvec[(size_t)NB * NR + m0 * NR + ridx];
        um[mf * 2 + 1] = uvec[m1 * NR + ridx] + uvec[(size_t)NB * NR + m1 * NR + ridx];
        ic[mf * 2 + 0] = invc[m0];
        ic[mf * 2 + 1] = invc[m1];
    }

#pragma unroll
    for (int ph = 0; ph < 2; ph++) {
        if (j == ph) {
#pragma unroll
            for (int mf = 0; mf < 2; mf++) {
                const int r0 = wm + mf * 16 + g;
#pragma unroll
                for (int nf = 0; nf < 8; nf++) {
                    const int s0 = nf * 8 + tg * 2;
                    const float b0 = sbm[j * 64 + s0];
                    const float b1 = sbm[j * 64 + s0 + 1];
                    const float d0 = sinvd[j * 64 + s0];
                    const float d1 = sinvd[j * 64 + s0 + 1];
                    const float W00 = (65536.f * (float)acch[mf][nf][0] + 256.f * (float)accm[mf][nf][0]) * ic[mf * 2] * d0;
                    const float W01 = (65536.f * (float)acch[mf][nf][1] + 256.f * (float)accm[mf][nf][1]) * ic[mf * 2] * d1;
                    const float W10 = (65536.f * (float)acch[mf][nf][2] + 256.f * (float)accm[mf][nf][2]) * ic[mf * 2 + 1] * d0;
                    const float W11 = (65536.f * (float)acch[mf][nf][3] + 256.f * (float)accm[mf][nf][3]) * ic[mf * 2 + 1] * d1;
                    part[r0 * 65 + s0]           += um[mf * 2] * (W00 + b0);
                    part[r0 * 65 + s0 + 1]       += um[mf * 2] * (W01 + b1);
                    part[(r0 + 8) * 65 + s0]     += um[mf * 2 + 1] * (W10 + b0);
                    part[(r0 + 8) * 65 + s0 + 1] += um[mf * 2 + 1] * (W11 + b1);
                }
            }
        }
        __syncthreads();
    }

    for (int idx = tid; idx < 128 * 64; idx += 256) {
        const int row = idx >> 6, s = idx & 63;
        out[((arow0 + row) * NT_W + nt) * NR + s] = part[row * 65 + s];
    }
}

// ---------------------------------------------------------------------------
// h[m,s] = sum_t hp[m,t,s]
// ---------------------------------------------------------------------------
__global__ __launch_bounds__(256)
void reduce_h(const float* __restrict__ hp, float* __restrict__ h)
{
    const int idx = blockIdx.x * 256 + threadIdx.x;
    const int m = idx >> 6, s = idx & 63;
    const float* p = hp + (size_t)m * (NT_W * NR) + s;
    float a = 0.f;
#pragma unroll
    for (int t = 0; t < NT_W; t++) a += p[t * NR];
    h[idx] = a;
}

// ---------------------------------------------------------------------------
// out[m,n] = act( sum_s h[m,s] * V[n,s] + bias[n] ), fp32 out
// ---------------------------------------------------------------------------
template<bool RELU>
__global__ __launch_bounds__(256)
void vgemm_k(const float* __restrict__ h, const float* __restrict__ V,
             const float* __restrict__ bias, float* __restrict__ out)
{
    __shared__ float hsT[64][68];
    __shared__ float vsT[64][68];
    const int m0 = blockIdx.y * 64;
    const int n0 = blockIdx.x * 64;
    const int tid = threadIdx.x;

    {
        const int r = tid >> 2;
        const int c = (tid & 3) * 16;
        const float4* hp = (const float4*)(h + (size_t)(m0 + r) * NR + c);
        const float4* vp = (const float4*)(V + (size_t)(n0 + r) * NR + c);
#pragma unroll
        for (int j = 0; j < 4; j++) {
            float4 hv = hp[j];
            hsT[c + 4 * j + 0][r] = hv.x; hsT[c + 4 * j + 1][r] = hv.y;
            hsT[c + 4 * j + 2][r] = hv.z; hsT[c + 4 * j + 3][r] = hv.w;
            float4 vv = vp[j];
            vsT[c + 4 * j + 0][r] = vv.x; vsT[c + 4 * j + 1][r] = vv.y;
            vsT[c + 4 * j + 2][r] = vv.z; vsT[c + 4 * j + 3][r] = vv.w;
        }
    }
    __syncthreads();

    const int tm = (tid >> 4) * 4;
    const int tn = (tid & 15) * 4;
    float acc[4][4];
#pragma unroll
    for (int i = 0; i < 4; i++)
#pragma unroll
        for (int j = 0; j < 4; j++) acc[i][j] = 0.f;

#pragma unroll
    for (int s = 0; s < 64; s++) {
        const float4 av = *(const float4*)&hsT[s][tm];
        const float4 bv = *(const float4*)&vsT[s][tn];
        const float a4[4] = {av.x, av.y, av.z, av.w};
        const float b4[4] = {bv.x, bv.y, bv.z, bv.w};
#pragma unroll
        for (int i = 0; i < 4; i++)
#pragma unroll
            for (int j = 0; j < 4; j++) acc[i][j] += a4[i] * b4[j];
    }

#pragma unroll
    for (int i = 0; i < 4; i++) {
        float v[4];
#pragma unroll
        for (int j = 0; j < 4; j++) {
            v[j] = acc[i][j] + bias[n0 + tn + j];
            if (RELU) v[j] = fmaxf(v[j], 0.f);
        }
        *(float4*)(out + (size_t)(m0 + tm + i) * ND + (n0 + tn)) =
            make_float4(v[0], v[1], v[2], v[3]);
    }
}

// ---------------------------------------------------------------------------
extern "C" void kernel_launch(void* const* d_in, const int* in_sizes, int n_in,
                              void* d_out, int out_size)
{
    const float* x = (const float*)d_in[0];

    __nv_bfloat16 *xhi, *xlo, *uhi, *ulo;
    char *xq1, *xq0, *wq1, *wq0;
    float *invc, *invd, *u2, *hp, *h, *act;
    cudaGetSymbolAddress((void**)&xhi, g_xhi);
    cudaGetSymbolAddress((void**)&xlo, g_xlo);
    cudaGetSymbolAddress((void**)&uhi, g_uhi);
    cudaGetSymbolAddress((void**)&ulo, g_ulo);
    cudaGetSymbolAddress((void**)&xq1, g_xq1);
    cudaGetSymbolAddress((void**)&xq0, g_xq0);
    cudaGetSymbolAddress((void**)&wq1, g_wq1);
    cudaGetSymbolAddress((void**)&wq0, g_wq0);
    cudaGetSymbolAddress((void**)&invc, g_invc);
    cudaGetSymbolAddress((void**)&invd, g_invd);
    cudaGetSymbolAddress((void**)&u2, g_u2);
    cudaGetSymbolAddress((void**)&hp, g_hp);
    cudaGetSymbolAddress((void**)&h,  g_h);
    cudaGetSymbolAddress((void**)&act, g_act);

    cudaFuncSetAttribute(gemm_u,  cudaFuncAttributeMaxDynamicSharedMemorySize, UB_SMEM);
    cudaFuncSetAttribute(gemm_s8, cudaFuncAttributeMaxDynamicSharedMemorySize, S8_SMEM);

    // layer-0 input: quantize + bf16 split
    quant_rows<true><<<NB, 256>>>(x, xq1, xq0, invc, xhi, xlo);

    for (int l = 0; l < 3; l++) {
        const float* Wm   = (const float*)d_in[1 + 5 * l + 0];
        const float* bm   = (const float*)d_in[1 + 5 * l + 1];
        const float* U    = (const float*)d_in[1 + 5 * l + 2];
        const float* V    = (const float*)d_in[1 + 5 * l + 3];
        const float* bias = (const float*)d_in[1 + 5 * l + 4];

        quant_rows<false><<<NRR, 256>>>(Wm, wq1, wq0, invd, nullptr, nullptr);
        conv_upad<<<(128 * ND / 4 + 255) / 256, 256>>>(
            U, (__nv_bfloat162*)uhi, (__nv_bfloat162*)ulo);

        // u = X @ U^T (3xBF16, K-split into 2 slices)
        gemm_u<<<dim3(2, NB / GBM), 256, UB_SMEM>>>(xhi, xlo, uhi, ulo, u2);

        // W-gen (int8 16-bit fixed point) + fused contract -> 32-way partials
        gemm_s8<<<dim3(NT_W, NB / GBM), 256, S8_SMEM>>>(
            xq1, xq0, wq1, wq0, invc, invd, u2, bm, hp);

        reduce_h<<<NB * NR / 256, 256>>>(hp, h);

        if (l < 2) {
            vgemm_k<true><<<dim3(ND / 64, NB / 64), 256>>>(h, V, bias, act);
            quant_rows<true><<<NB, 256>>>(act, xq1, xq0, invc, xhi, xlo);
        } else {
            vgemm_k<false><<<dim3(ND / 64, NB / 64), 256>>>(h, V, bias, (float*)d_out);
        }
    }
}

// round 16
// speedup vs baseline: 3.5279x; 3.5279x over previous
#include <cuda_runtime.h>
#include <cuda_fp16.h>
#include <cstdint>

// ---------------- problem constants ----------------
#define NB   8192
#define ND   1024
#define NR   64
#define NRR  4096
#define NT_W 32              // 4096 / 128

// ---------------- W-gemm tiling (fp16, 2-pass, BKE=32) ----------------
#define GBM 128
#define GBN 128
#define W_LDSW 20            // u32 row stride (16 + 4 skew) = 80B
#define W_MAT   (128 * W_LDSW * 4)   // 10240 bytes per matrix tile
#define W_STAGE (3 * W_MAT)          // Ahi, Alo, B = 30720
#define W_SMEM  (2 * W_STAGE)        // 61440

// ---------------- u-gemm tiling (fp16, 3-pass, BKE=64) ----------------
#define UB_LDSW 36           // u32 row stride (32 + 4 skew)
#define UB_MAT   (128 * UB_LDSW * 4) // 18432
#define UB_STAGE (4 * UB_MAT)        // 73728
#define UB_SMEM  (2 * UB_STAGE)      // 147456

// ---------------- static device scratch ----------------
__device__ __half g_xhi[(size_t)NB * ND];
__device__ __half g_xlo[(size_t)NB * ND];
__device__ __half g_w16[(size_t)NRR * ND];
__device__ __half g_uhi[(size_t)128 * ND];   // U padded to 128 rows
__device__ __half g_ulo[(size_t)128 * ND];
__device__ float g_u2[(size_t)2 * NB * NR];  // 2 K-slice partials of u
__device__ float g_hp[(size_t)NB * NT_W * NR];
__device__ float g_h [(size_t)NB * NR];

// ---------------- helpers ----------------
__device__ __forceinline__ uint32_t smem_u32(const void* p) {
    uint32_t a;
    asm("{ .reg .u64 t; cvta.to.shared.u64 t, %1; cvt.u32.u64 %0, t; }"
        : "=r"(a) : "l"(p));
    return a;
}
__device__ __forceinline__ void cpa16(uint32_t s, const void* g) {
    asm volatile("cp.async.cg.shared.global [%0], [%1], 16;\n" :: "r"(s), "l"(g));
}
#define CP_COMMIT() asm volatile("cp.async.commit_group;\n" ::: "memory")
#define CP_WAIT(n)  asm volatile("cp.async.wait_group %0;\n" :: "n"(n) : "memory")

#define MMA_F16(acc, a0, a1, a2, a3, b0, b1)                                   \
    asm("mma.sync.aligned.m16n8k16.row.col.f32.f16.f16.f32 "                   \
        "{%0,%1,%2,%3}, {%4,%5,%6,%7}, {%8,%9}, {%0,%1,%2,%3};\n"              \
        : "+f"(acc[0]), "+f"(acc[1]), "+f"(acc[2]), "+f"(acc[3])               \
        : "r"(a0), "r"(a1), "r"(a2), "r"(a3), "r"(b0), "r"(b1))

#define LDSM_X4(r, addr)                                                       \
    asm volatile("ldmatrix.sync.aligned.m8n8.x4.shared.b16 {%0,%1,%2,%3}, [%4];" \
        : "=r"((r)[0]), "=r"((r)[1]), "=r"((r)[2]), "=r"((r)[3]) : "r"(addr))

// ---------------------------------------------------------------------------
// u-GEMM: fp16 3-pass (Ah*Bh + Ah*Bl + Al*Bh), BKE=64.
// blockIdx.x = K-slice (0/1); stores D cols [0,64) to out + slice*NB*NR.
// ---------------------------------------------------------------------------
__global__ __launch_bounds__(256)
void gemm_u(const __half* __restrict__ Ahi_g, const __half* __restrict__ Alo_g,
            const __half* __restrict__ Bhi_g, const __half* __restrict__ Blo_g,
            float* __restrict__ out)
{
    extern __shared__ char dynsmem[];
    const uint32_t sbase = smem_u32(dynsmem);

    const int tid = threadIdx.x, warp = tid >> 5, lane = tid & 31;
    const int wm = (warp & 3) * 32, wn = (warp >> 2) * 64;
    const int g = lane >> 2, tg = lane & 3;
    const int nt = blockIdx.x, mt = blockIdx.y;
    const size_t arow0 = (size_t)mt * GBM;
    const int kbase = nt * (ND / 2);

    float acc[2][8][4];
#pragma unroll
    for (int i = 0; i < 2; i++)
#pragma unroll
        for (int j = 0; j < 8; j++)
#pragma unroll
            for (int k = 0; k < 4; k++) acc[i][j][k] = 0.f;

    const int l8 = lane & 7;
    uint32_t aOffB[2], bOffB[4];
#pragma unroll
    for (int mf = 0; mf < 2; mf++)
        aOffB[mf] = (uint32_t)(((wm + mf * 16 + l8 + ((lane >> 3) & 1) * 8) * UB_LDSW
                                + (lane >> 4) * 4) * 4);
#pragma unroll
    for (int p = 0; p < 4; p++)
        bOffB[p] = (uint32_t)(((wn + p * 16 + l8 + ((lane >> 4) & 1) * 8) * UB_LDSW
                               + ((lane >> 3) & 1) * 4) * 4);

    auto load_stage = [&](int stage, int buf) {
        const uint32_t base = sbase + buf * UB_STAGE;
        const int k0 = kbase + stage * 64;
#pragma unroll
        for (int it = 0; it < 4; it++) {
            const int t = tid + it * 256;
            const int row = t >> 3, c = t & 7;
            const uint32_t so = (uint32_t)(row * (UB_LDSW * 4) + c * 16);
            const size_t ga = (arow0 + row) * ND + k0 + c * 8;
            const size_t gb = (size_t)row * ND + k0 + c * 8;
            cpa16(base + so,              Ahi_g + ga);
            cpa16(base + UB_MAT + so,     Alo_g + ga);
            cpa16(base + 2 * UB_MAT + so, Bhi_g + gb);
            cpa16(base + 3 * UB_MAT + so, Blo_g + gb);
        }
        CP_COMMIT();
    };

    load_stage(0, 0);

    for (int i = 0; i < 8; i++) {
        if (i + 1 < 8) { load_stage(i + 1, (i + 1) & 1); CP_WAIT(1); }
        else           { CP_WAIT(0); }
        __syncthreads();

        const uint32_t stb = sbase + (i & 1) * UB_STAGE;
#pragma unroll
        for (int ks = 0; ks < 4; ks++) {
            const uint32_t kob = (uint32_t)(ks * 32);
            uint32_t ah[2][4], al[2][4], bh[4][4], bl[4][4];
#pragma unroll
            for (int mf = 0; mf < 2; mf++) {
                LDSM_X4(ah[mf], stb + aOffB[mf] + kob);
                LDSM_X4(al[mf], stb + UB_MAT + aOffB[mf] + kob);
            }
#pragma unroll
            for (int p = 0; p < 4; p++) {
                LDSM_X4(bh[p], stb + 2 * UB_MAT + bOffB[p] + kob);
                LDSM_X4(bl[p], stb + 3 * UB_MAT + bOffB[p] + kob);
            }
#pragma unroll
            for (int p = 0; p < 4; p++)
#pragma unroll
                for (int mf = 0; mf < 2; mf++) {
                    MMA_F16(acc[mf][2 * p],     ah[mf][0], ah[mf][1], ah[mf][2], ah[mf][3], bh[p][0], bh[p][1]);
                    MMA_F16(acc[mf][2 * p + 1], ah[mf][0], ah[mf][1], ah[mf][2], ah[mf][3], bh[p][2], bh[p][3]);
                }
#pragma unroll
            for (int p = 0; p < 4; p++)
#pragma unroll
                for (int mf = 0; mf < 2; mf++) {
                    MMA_F16(acc[mf][2 * p],     ah[mf][0], ah[mf][1], ah[mf][2], ah[mf][3], bl[p][0], bl[p][1]);
                    MMA_F16(acc[mf][2 * p + 1], ah[mf][0], ah[mf][1], ah[mf][2], ah[mf][3], bl[p][2], bl[p][3]);
                }
#pragma unroll
            for (int p = 0; p < 4; p++)
#pragma unroll
                for (int mf = 0; mf < 2; mf++) {
                    MMA_F16(acc[mf][2 * p],     al[mf][0], al[mf][1], al[mf][2], al[mf][3], bh[p][0], bh[p][1]);
                    MMA_F16(acc[mf][2 * p + 1], al[mf][0], al[mf][1], al[mf][2], al[mf][3], bh[p][2], bh[p][3]);
                }
        }
        __syncthreads();
    }

    float* o = out + (size_t)nt * NB * NR;
    if (wn == 0) {
#pragma unroll
        for (int mf = 0; mf < 2; mf++) {
#pragma unroll
            for (int nf = 0; nf < 8; nf++) {
                const size_t row = arow0 + wm + mf * 16 + g;
                const int col = nf * 8 + tg * 2;
                *(float2*)(o + row * NR + col) =
                    make_float2(acc[mf][nf][0], acc[mf][nf][1]);
                *(float2*)(o + (row + 8) * NR + col) =
                    make_float2(acc[mf][nf][2], acc[mf][nf][3]);
            }
        }
    }
}

// ---------------------------------------------------------------------------
// W-GEMM: fp16 2-pass (Ahi*B + Alo*B), BKE=32, + fused contract epilogue.
// Error source: only Wm fp16 rounding (~1.4e-4 per GEMM).
// Emits hp[m][nt][s] = sum_j u[m, nt*2+j] * (W[m, j*64+s] + bm[...]),
// where u[m,r] = uvec[m*NR+r] + uvec[NB*NR + m*NR+r].
// ---------------------------------------------------------------------------
__global__ __launch_bounds__(256, 2)
void gemm_w(const __half* __restrict__ Ahi_g, const __half* __restrict__ Alo_g,
            const __half* __restrict__ Bg,
            const float* __restrict__ uvec, const float* __restrict__ bmvec,
            float* __restrict__ out)
{
    extern __shared__ char dynsmem[];
    __shared__ float sbm[GBN];
    const uint32_t sbase = smem_u32(dynsmem);

    const int tid = threadIdx.x, warp = tid >> 5, lane = tid & 31;
    const int wm = (warp & 3) * 32, wn = (warp >> 2) * 64;
    const int g = lane >> 2, tg = lane & 3;
    const int nt = blockIdx.x, mt = blockIdx.y;
    const size_t arow0 = (size_t)mt * GBM;
    const size_t brow0 = (size_t)nt * GBN;

    if (tid < GBN) sbm[tid] = bmvec[nt * GBN + tid];

    float acc[2][8][4];
#pragma unroll
    for (int i = 0; i < 2; i++)
#pragma unroll
        for (int j = 0; j < 8; j++)
#pragma unroll
            for (int k = 0; k < 4; k++) acc[i][j][k] = 0.f;

    const int l8 = lane & 7;
    uint32_t aOffB[2], bOffB[4];
#pragma unroll
    for (int mf = 0; mf < 2; mf++)
        aOffB[mf] = (uint32_t)(((wm + mf * 16 + l8 + ((lane >> 3) & 1) * 8) * W_LDSW
                                + (lane >> 4) * 4) * 4);
#pragma unroll
    for (int p = 0; p < 4; p++)
        bOffB[p] = (uint32_t)(((wn + p * 16 + l8 + ((lane >> 4) & 1) * 8) * W_LDSW
                               + ((lane >> 3) & 1) * 4) * 4);

    // 3 matrices x 128 rows x 2 x16B per 512 units -> 6 cp.async/thread
    auto load_stage = [&](int stage, int buf) {
        const uint32_t base = sbase + buf * W_STAGE;
        const int k0 = stage * 32;
#pragma unroll
        for (int it = 0; it < 2; it++) {
            const int t = tid + it * 256;          // 0..511
            const int row = t >> 2, c = t & 3;
            const uint32_t so = (uint32_t)(row * (W_LDSW * 4) + c * 16);
            const size_t ga = (arow0 + row) * ND + k0 + c * 8;
            const size_t gb = (brow0 + row) * ND + k0 + c * 8;
            cpa16(base + so,             Ahi_g + ga);
            cpa16(base + W_MAT + so,     Alo_g + ga);
            cpa16(base + 2 * W_MAT + so, Bg + gb);
        }
        CP_COMMIT();
    };

    load_stage(0, 0);

    for (int i = 0; i < ND / 32; i++) {            // 32 stages
        if (i + 1 < ND / 32) { load_stage(i + 1, (i + 1) & 1); CP_WAIT(1); }
        else                 { CP_WAIT(0); }
        __syncthreads();

        const uint32_t stb = sbase + (i & 1) * W_STAGE;
#pragma unroll
        for (int ks = 0; ks < 2; ks++) {
            const uint32_t kob = (uint32_t)(ks * 32);
            uint32_t ah[2][4], al[2][4], bf[4][4];
#pragma unroll
            for (int mf = 0; mf < 2; mf++) {
                LDSM_X4(ah[mf], stb + aOffB[mf] + kob);
                LDSM_X4(al[mf], stb + W_MAT + aOffB[mf] + kob);
            }
#pragma unroll
            for (int p = 0; p < 4; p++)
                LDSM_X4(bf[p], stb + 2 * W_MAT + bOffB[p] + kob);
            // pass 1: Ahi * B
#pragma unroll
            for (int p = 0; p < 4; p++)
#pragma unroll
                for (int mf = 0; mf < 2; mf++) {
                    MMA_F16(acc[mf][2 * p],     ah[mf][0], ah[mf][1], ah[mf][2], ah[mf][3], bf[p][0], bf[p][1]);
                    MMA_F16(acc[mf][2 * p + 1], ah[mf][0], ah[mf][1], ah[mf][2], ah[mf][3], bf[p][2], bf[p][3]);
                }
            // pass 2: Alo * B
#pragma unroll
            for (int p = 0; p < 4; p++)
#pragma unroll
                for (int mf = 0; mf < 2; mf++) {
                    MMA_F16(acc[mf][2 * p],     al[mf][0], al[mf][1], al[mf][2], al[mf][3], bf[p][0], bf[p][1]);
                    MMA_F16(acc[mf][2 * p + 1], al[mf][0], al[mf][1], al[mf][2], al[mf][3], bf[p][2], bf[p][3]);
                }
        }
        __syncthreads();
    }

    // ---- fused contract epilogue (part[128][65] reuses operand smem) ----
    float* part = (float*)dynsmem;
    for (int idx = tid; idx < 128 * 65; idx += 256) part[idx] = 0.f;
    __syncthreads();

    const int j = warp >> 2;                       // r-block within tile (0/1)
    const int ridx = nt * 2 + j;
    float um[4];
#pragma unroll
    for (int mf = 0; mf < 2; mf++) {
        const size_t r0 = (arow0 + wm + mf * 16 + g) * NR + ridx;
        const size_t r1 = (arow0 + wm + mf * 16 + 8 + g) * NR + ridx;
        um[mf * 2 + 0] = uvec[r0] + uvec[(size_t)NB * NR + r0];
        um[mf * 2 + 1] = uvec[r1] + uvec[(size_t)NB * NR + r1];
    }

#pragma unroll
    for (int ph = 0; ph < 2; ph++) {
        if (j == ph) {
#pragma unroll
            for (int mf = 0; mf < 2; mf++) {
                const int r0 = wm + mf * 16 + g;
#pragma unroll
                for (int nf = 0; nf < 8; nf++) {
                    const int s0 = nf * 8 + tg * 2;
                    const float b0 = sbm[j * 64 + s0];
                    const float b1 = sbm[j * 64 + s0 + 1];
                    part[r0 * 65 + s0]           += um[mf * 2] * (acc[mf][nf][0] + b0);
                    part[r0 * 65 + s0 + 1]       += um[mf * 2] * (acc[mf][nf][1] + b1);
                    part[(r0 + 8) * 65 + s0]     += um[mf * 2 + 1] * (acc[mf][nf][2] + b0);
                    part[(r0 + 8) * 65 + s0 + 1] += um[mf * 2 + 1] * (acc[mf][nf][3] + b1);
                }
            }
        }
        __syncthreads();
    }

    for (int idx = tid; idx < 128 * 64; idx += 256) {
        const int row = idx >> 6, s = idx & 63;
        out[((arow0 + row) * NT_W + nt) * NR + s] = part[row * 65 + s];
    }
}

// ---------------------------------------------------------------------------
// h[m,s] = sum_t hp[m,t,s]
// ---------------------------------------------------------------------------
__global__ __launch_bounds__(256)
void reduce_h(const float* __restrict__ hp, float* __restrict__ h)
{
    const int idx = blockIdx.x * 256 + threadIdx.x;
    const int m = idx >> 6, s = idx & 63;
    const float* p = hp + (size_t)m * (NT_W * NR) + s;
    float a = 0.f;
#pragma unroll
    for (int t = 0; t < NT_W; t++) a += p[t * NR];
    h[idx] = a;
}

// ---------------------------------------------------------------------------
// out[m,n] = act( sum_s h[m,s] * V[n,s] + bias[n] )
// F16OUT: emit fp16 hi/lo split directly (feeds next layer's GEMMs)
// ---------------------------------------------------------------------------
template<bool RELU, bool F16OUT>
__global__ __launch_bounds__(256)
void vgemm_k(const float* __restrict__ h, const float* __restrict__ V,
             const float* __restrict__ bias, float* __restrict__ out,
             __half* __restrict__ ohi, __half* __restrict__ olo)
{
    __shared__ float hsT[64][68];
    __shared__ float vsT[64][68];
    const int m0 = blockIdx.y * 64;
    const int n0 = blockIdx.x * 64;
    const int tid = threadIdx.x;

    {
        const int r = tid >> 2;
        const int c = (tid & 3) * 16;
        const float4* hp = (const float4*)(h + (size_t)(m0 + r) * NR + c);
        const float4* vp = (const float4*)(V + (size_t)(n0 + r) * NR + c);
#pragma unroll
        for (int j = 0; j < 4; j++) {
            float4 hv = hp[j];
            hsT[c + 4 * j + 0][r] = hv.x; hsT[c + 4 * j + 1][r] = hv.y;
            hsT[c + 4 * j + 2][r] = hv.z; hsT[c + 4 * j + 3][r] = hv.w;
            float4 vv = vp[j];
            vsT[c + 4 * j + 0][r] = vv.x; vsT[c + 4 * j + 1][r] = vv.y;
            vsT[c + 4 * j + 2][r] = vv.z; vsT[c + 4 * j + 3][r] = vv.w;
        }
    }
    __syncthreads();

    const int tm = (tid >> 4) * 4;
    const int tn = (tid & 15) * 4;
    float acc[4][4];
#pragma unroll
    for (int i = 0; i < 4; i++)
#pragma unroll
        for (int j = 0; j < 4; j++) acc[i][j] = 0.f;

#pragma unroll
    for (int s = 0; s < 64; s++) {
        const float4 av = *(const float4*)&hsT[s][tm];
        const float4 bv = *(const float4*)&vsT[s][tn];
        const float a4[4] = {av.x, av.y, av.z, av.w};
        const float b4[4] = {bv.x, bv.y, bv.z, bv.w};
#pragma unroll
        for (int i = 0; i < 4; i++)
#pragma unroll
            for (int j = 0; j < 4; j++) acc[i][j] += a4[i] * b4[j];
    }

#pragma unroll
    for (int i = 0; i < 4; i++) {
        float v[4];
#pragma unroll
        for (int j = 0; j < 4; j++) {
            v[j] = acc[i][j] + bias[n0 + tn + j];
            if (RELU) v[j] = fmaxf(v[j], 0.f);
        }
        const size_t o = (size_t)(m0 + tm + i) * ND + (n0 + tn);
        if (F16OUT) {
            __half hh[4], ll[4];
#pragma unroll
            for (int j = 0; j < 4; j++) {
                hh[j] = __float2half_rn(v[j]);
                ll[j] = __float2half_rn(v[j] - __half2float(hh[j]));
            }
            *(__half2*)(ohi + o)     = __halves2half2(hh[0], hh[1]);
            *(__half2*)(ohi + o + 2) = __halves2half2(hh[2], hh[3]);
            *(__half2*)(olo + o)     = __halves2half2(ll[0], ll[1]);
            *(__half2*)(olo + o + 2) = __halves2half2(ll[2], ll[3]);
        } else {
            *(float4*)(out + o) = make_float4(v[0], v[1], v[2], v[3]);
        }
    }
}

// ---------------------------------------------------------------------------
// fp32 -> fp16 hi/lo split (elementwise, float4 vectorized)
// ---------------------------------------------------------------------------
__global__ __launch_bounds__(256)
void conv_split16(const float4* __restrict__ in, __half2* __restrict__ hi,
                  __half2* __restrict__ lo, int n4)
{
    const int i = blockIdx.x * 256 + threadIdx.x;
    if (i >= n4) return;
    const float4 v = in[i];
    const float f[4] = {v.x, v.y, v.z, v.w};
    __half hh[4], ll[4];
#pragma unroll
    for (int j = 0; j < 4; j++) {
        hh[j] = __float2half_rn(f[j]);
        ll[j] = __float2half_rn(f[j] - __half2float(hh[j]));
    }
    hi[2 * i]     = __halves2half2(hh[0], hh[1]);
    hi[2 * i + 1] = __halves2half2(hh[2], hh[3]);
    lo[2 * i]     = __halves2half2(ll[0], ll[1]);
    lo[2 * i + 1] = __halves2half2(ll[2], ll[3]);
}

// fp32 -> single fp16 plane (for Wm)
__global__ __launch_bounds__(256)
void conv_f16(const float4* __restrict__ in, __half2* __restrict__ o16, int n4)
{
    const int i = blockIdx.x * 256 + threadIdx.x;
    if (i >= n4) return;
    const float4 v = in[i];
    o16[2 * i]     = __halves2half2(__float2half_rn(v.x), __float2half_rn(v.y));
    o16[2 * i + 1] = __halves2half2(__float2half_rn(v.z), __float2half_rn(v.w));
}

// U [64 x 1024] -> padded [128 x 1024] fp16 hi/lo with zero rows 64..127
__global__ __launch_bounds__(256)
void conv_upad16(const float* __restrict__ U, __half2* __restrict__ hi,
                 __half2* __restrict__ lo)
{
    const int i = blockIdx.x * 256 + threadIdx.x;
    if (i >= 128 * ND / 4) return;
    const int row = (i * 4) >> 10;
    float4 v = make_float4(0.f, 0.f, 0.f, 0.f);
    if (row < NR) v = ((const float4*)U)[i];
    const float f[4] = {v.x, v.y, v.z, v.w};
    __half hh[4], ll[4];
#pragma unroll
    for (int j = 0; j < 4; j++) {
        hh[j] = __float2half_rn(f[j]);
        ll[j] = __float2half_rn(f[j] - __half2float(hh[j]));
    }
    hi[2 * i]     = __halves2half2(hh[0], hh[1]);
    hi[2 * i + 1] = __halves2half2(hh[2], hh[3]);
    lo[2 * i]     = __halves2half2(ll[0], ll[1]);
    lo[2 * i + 1] = __halves2half2(ll[2], ll[3]);
}

// ---------------------------------------------------------------------------
extern "C" void kernel_launch(void* const* d_in, const int* in_sizes, int n_in,
                              void* d_out, int out_size)
{
    const float* x = (const float*)d_in[0];

    __half *xhi, *xlo, *w16, *uhi, *ulo;
    float *u2, *hp, *h;
    cudaGetSymbolAddress((void**)&xhi, g_xhi);
    cudaGetSymbolAddress((void**)&xlo, g_xlo);
    cudaGetSymbolAddress((void**)&w16, g_w16);
    cudaGetSymbolAddress((void**)&uhi, g_uhi);
    cudaGetSymbolAddress((void**)&ulo, g_ulo);
    cudaGetSymbolAddress((void**)&u2, g_u2);
    cudaGetSymbolAddress((void**)&hp, g_hp);
    cudaGetSymbolAddress((void**)&h,  g_h);

    cudaFuncSetAttribute(gemm_u, cudaFuncAttributeMaxDynamicSharedMemorySize, UB_SMEM);
    cudaFuncSetAttribute(gemm_w, cudaFuncAttributeMaxDynamicSharedMemorySize, W_SMEM);

    // split layer-0 input
    conv_split16<<<(NB * ND / 4 + 255) / 256, 256>>>(
        (const float4*)x, (__half2*)xhi, (__half2*)xlo, NB * ND / 4);

    for (int l = 0; l < 3; l++) {
        const float* Wm   = (const float*)d_in[1 + 5 * l + 0];
        const float* bm   = (const float*)d_in[1 + 5 * l + 1];
        const float* U    = (const float*)d_in[1 + 5 * l + 2];
        const float* V    = (const float*)d_in[1 + 5 * l + 3];
        const float* bias = (const float*)d_in[1 + 5 * l + 4];

        conv_f16<<<(NRR * ND / 4 + 255) / 256, 256>>>(
            (const float4*)Wm, (__half2*)w16, NRR * ND / 4);
        conv_upad16<<<(128 * ND / 4 + 255) / 256, 256>>>(
            U, (__half2*)uhi, (__half2*)ulo);

        // u = X @ U^T (fp16 3-pass, K-split into 2 slices)
        gemm_u<<<dim3(2, NB / GBM), 256, UB_SMEM>>>(xhi, xlo, uhi, ulo, u2);

        // W-gen (fp16 2-pass) + fused contract -> 32-way partials of h
        gemm_w<<<dim3(NT_W, NB / GBM), 256, W_SMEM>>>(
            xhi, xlo, w16, u2, bm, hp);

        reduce_h<<<NB * NR / 256, 256>>>(hp, h);

        if (l < 2)
            vgemm_k<true, true><<<dim3(ND / 64, NB / 64), 256>>>(
                h, V, bias, nullptr, xhi, xlo);
        else
            vgemm_k<false, false><<<dim3(ND / 64, NB / 64), 256>>>(
                h, V, bias, (float*)d_out, nullptr, nullptr);
    }
}